// round 1
// baseline (speedup 1.0000x reference)
#include <cuda_runtime.h>
#include <math.h>

#ifndef M_PI
#define M_PI 3.14159265358979323846
#endif

#define Nk 1024
#define Lk 4096
#define Pk 8192
#define TA 256
#define CHA (Lk/TA)     // 16 elements per thread in stage A
#define TB 512
#define CHB (Pk/TB)     // 16 elements per thread in stage B

// Scratch (no cudaMalloc allowed): interpolated acquired spectra + twiddle table
__device__ float  g_acq[(size_t)Nk * Pk];     // 32 MB
__device__ float2 g_tw[Pk / 2];               // 32 KB: exp(-2*pi*i*r/P), r in [0, P/2)

// ---------------------------------------------------------------------------
// Twiddle init (fp64-accurate)
// ---------------------------------------------------------------------------
__global__ void twiddle_init() {
    int i = blockIdx.x * blockDim.x + threadIdx.x;
    if (i < Pk / 2) {
        double ang = -2.0 * M_PI * (double)i / (double)Pk;
        g_tw[i] = make_float2((float)cos(ang), (float)sin(ang));
    }
}

// ---------------------------------------------------------------------------
// Block helpers (256 threads = 8 warps in stage A)
// ---------------------------------------------------------------------------
__device__ __forceinline__ double blockExScan(double x, double* wsum, double* woff) {
    const unsigned full = 0xffffffffu;
    int lane = threadIdx.x & 31, wid = threadIdx.x >> 5;
    int nw = blockDim.x >> 5;
    double inc = x;
#pragma unroll
    for (int o = 1; o < 32; o <<= 1) {
        double y = __shfl_up_sync(full, inc, o);
        if (lane >= o) inc += y;
    }
    if (lane == 31) wsum[wid] = inc;
    __syncthreads();
    if (threadIdx.x == 0) {
        double run = 0.0;
        for (int i = 0; i < nw; i++) { double t = wsum[i]; woff[i] = run; run += t; }
    }
    __syncthreads();
    double r = woff[wid] + inc - x;
    __syncthreads();   // protect wsum/woff for reuse
    return r;
}

__device__ __forceinline__ float blockMax(float x, float* red) {
    const unsigned full = 0xffffffffu;
    int lane = threadIdx.x & 31, wid = threadIdx.x >> 5;
    int nw = blockDim.x >> 5;
#pragma unroll
    for (int o = 16; o > 0; o >>= 1)
        x = fmaxf(x, __shfl_xor_sync(full, x, o));
    if (lane == 0) red[wid] = x;
    __syncthreads();
    if (threadIdx.x == 0) {
        float m = red[0];
        for (int i = 1; i < nw; i++) m = fmaxf(m, red[i]);
        red[0] = m;
    }
    __syncthreads();
    float r = red[0];
    __syncthreads();   // protect red for reuse
    return r;
}

// ---------------------------------------------------------------------------
// Stage A: walk -> smooth -> detrend/normalize -> interp onto ppm grid
// one block per batch row
// ---------------------------------------------------------------------------
__global__ void __launch_bounds__(TA) stageA(
    const float* __restrict__ start_, const float* __restrict__ end_,
    const float* __restrict__ stdv,   const float* __restrict__ lob,
    const float* __restrict__ upb,    const int*   __restrict__ win,
    const float* __restrict__ scl,    const float* __restrict__ noise,
    const float* __restrict__ omit,   const float* __restrict__ ppm,
    const float* __restrict__ rng)
{
    extern __shared__ char smem[];
    float*  sA   = (float*)smem;                                  // Lk floats
    double* csD  = (double*)(smem + Lk * 4);                      // Lk+1 doubles
    double* wsum = (double*)(smem + Lk * 4 + (Lk + 1) * 8);       // 8 doubles
    double* woff = wsum + 8;                                      // 8 doubles
    float*  redf = (float*)(woff + 8);                            // 8 floats
    float*  sbc  = redf + 8;                                      // 2 floats

    const int n = blockIdx.x, t = threadIdx.x;
    const int base = t * CHA;
    const float stdn = stdv[n];
    const float inv = 1.0f / (float)(Lk - 1);

    // 1) steps + inclusive cumsum (fp64 accumulation)
    float v[CHA];
    double s = 0.0;
    const float4* nz4 = (const float4*)(noise + (size_t)n * Lk);
#pragma unroll
    for (int q = 0; q < CHA / 4; q++) {
        float4 nv = nz4[t * (CHA / 4) + q];
        float a0 = stdn * (nv.x - 0.5f), a1 = stdn * (nv.y - 0.5f);
        float a2 = stdn * (nv.z - 0.5f), a3 = stdn * (nv.w - 0.5f);
        v[q * 4 + 0] = a0; v[q * 4 + 1] = a1; v[q * 4 + 2] = a2; v[q * 4 + 3] = a3;
        s += (double)a0 + (double)a1 + (double)a2 + (double)a3;
    }
    double off = blockExScan(s, wsum, woff);
#pragma unroll
    for (int i = 0; i < CHA; i++) { off += (double)v[i]; sA[base + i] = (float)off; }
    __syncthreads();

    // 2) detrend walk, find span
    const float r0 = sA[0], rN = sA[Lk - 1];
    float mn = 1e30f, mx = -1e30f;
#pragma unroll
    for (int i = 0; i < CHA; i++) {
        int idx = base + i;
        float tt = (float)idx * inv;
        float d = sA[idx] - (r0 + (rN - r0) * tt);
        v[i] = d;
        mn = fminf(mn, d); mx = fmaxf(mx, d);
    }
    float gmx = blockMax(mx, redf);
    float gmn = -blockMax(-mn, redf);
    float span = gmx - gmn;
    const float lo = lob[n], up = upb[n];
    const float f = 1.0f / fmaxf(1.0f, span / (up - lo));
    const float st = start_[n], en = end_[n];

    // 3) squeeze + reflect + re-add trend -> walk; accumulate for cumsum
    double s2 = 0.0;
#pragma unroll
    for (int i = 0; i < CHA; i++) {
        int idx = base + i;
        float tt = (float)idx * inv;
        float tr = st + (en - st) * tt;
        float d = v[i] * f;
        float ub = up - tr, lb2 = lo - tr;
        float over = d - ub;
        if (over >= 0.0f) d = ub - over;
        float under = lb2 - d;
        if (under >= 0.0f) d = lb2 + under;
        float w = tr + d;
        v[i] = w;
        s2 += (double)w;
    }
    double off2 = blockExScan(s2, wsum, woff);
#pragma unroll
    for (int i = 0; i < CHA; i++) { csD[base + i] = off2; off2 += (double)v[i]; }
    if (t == TA - 1) csD[Lk] = off2;
    __syncthreads();

    // 4) box smoothing via prefix sums (zero padding == clamp)
    const int w = win[n];
    const int h2 = w >> 1;
    const double invw = 1.0 / (double)w;
#pragma unroll
    for (int i = 0; i < CHA; i++) {
        int idx = base + i;
        int loI = idx - h2;
        int hiI = loI + w;
        loI = max(0, min(loI, Lk));
        hiI = max(0, min(hiI, Lk));
        v[i] = (float)((csD[hiI] - csD[loI]) * invw);
    }
    if (t == 0)      sbc[0] = v[0];
    if (t == TA - 1) sbc[1] = v[CHA - 1];
    __syncthreads();
    const float b0 = sbc[0], bL = sbc[1];

    // 5) detrend smoothed + normalize + omit + scale
    float mxa = 0.0f;
#pragma unroll
    for (int i = 0; i < CHA; i++) {
        int idx = base + i;
        float tt = (float)idx * inv;
        float c = v[i] - (b0 + (bL - b0) * tt);
        v[i] = c;
        mxa = fmaxf(mxa, fabsf(c));
    }
    float denom = blockMax(mxa, redf);
    if (denom == 0.0f) denom = 1.0f;
    const float g = omit[n] * scl[n] / denom;
#pragma unroll
    for (int i = 0; i < CHA; i++) sA[base + i] = v[i] * g;
    __syncthreads();

    // 6) linear interp onto acquired ppm axis (zero outside simulated range)
    const float plo = rng[0], phi = rng[1];
    const float kk = (float)(Lk - 1) / (phi - plo);
    float* acq = g_acq + (size_t)n * Pk;
    for (int p = t; p < Pk; p += TA) {
        float pv = ppm[p];
        float o = 0.0f;
        if (pv >= plo && pv <= phi) {
            float pos = (pv - plo) * kk;
            int i0 = (int)pos;
            if (i0 > Lk - 2) i0 = Lk - 2;
            float fr = pos - (float)i0;
            float a = sA[i0];
            o = a + (sA[i0 + 1] - a) * fr;
        }
        acq[p] = o;
    }
}

// ---------------------------------------------------------------------------
// Stage B: pair-packed Hilbert via in-place radix-2 DIF -> H -> DIT
// one block per 2 rows
// ---------------------------------------------------------------------------
__global__ void __launch_bounds__(TB) stageB(float* __restrict__ out)
{
    extern __shared__ char smem[];
    float2* z  = (float2*)smem;               // Pk complex
    float2* tw = (float2*)(smem + Pk * 8);    // Pk/2 twiddles

    const int blk = blockIdx.x, t = threadIdx.x;
    const int r0 = blk * 2, r1 = r0 + 1;
    const float* a0 = g_acq + (size_t)r0 * Pk;
    const float* a1 = g_acq + (size_t)r1 * Pk;

    float x0[CHB], x1[CHB];
#pragma unroll
    for (int i = 0; i < CHB; i++) {
        int j = t + i * TB;
        x0[i] = a0[j];
        x1[i] = a1[j];
        z[j] = make_float2(x0[i], x1[i]);
    }
    for (int j = t; j < Pk / 2; j += TB) tw[j] = g_tw[j];
    __syncthreads();

    // forward DIF (natural in -> bit-reversed out)
    int mult = 1;
    for (int len = Pk; len >= 2; len >>= 1) {
        int half = len >> 1;
        for (int it = t; it < Pk / 2; it += TB) {
            int j = it & (half - 1);
            int b2 = ((it & ~(half - 1)) << 1) | j;
            float2 u = z[b2], vq = z[b2 + half];
            float dx = u.x - vq.x, dy = u.y - vq.y;
            float2 w = tw[j * mult];
            z[b2]        = make_float2(u.x + vq.x, u.y + vq.y);
            z[b2 + half] = make_float2(dx * w.x - dy * w.y, dx * w.y + dy * w.x);
        }
        mult <<= 1;
        __syncthreads();
    }

    // H multiply at bit-reversed frequency, fused 1/P scale
    const float s1 = 1.0f / (float)Pk, s2 = 2.0f / (float)Pk;
    for (int j = t; j < Pk; j += TB) {
        int k = (int)(__brev((unsigned)j) >> 19);   // 13-bit reverse
        float fH = (k == 0 || k == Pk / 2) ? s1 : (k < Pk / 2 ? s2 : 0.0f);
        float2 vq = z[j];
        z[j] = make_float2(vq.x * fH, vq.y * fH);
    }
    __syncthreads();

    // inverse DIT (bit-reversed in -> natural out), conj twiddles
    mult = Pk / 2;
    for (int len = 2; len <= Pk; len <<= 1) {
        int half = len >> 1;
        for (int it = t; it < Pk / 2; it += TB) {
            int j = it & (half - 1);
            int b2 = ((it & ~(half - 1)) << 1) | j;
            float2 u = z[b2], vq = z[b2 + half];
            float2 w = tw[j * mult];
            float vx = vq.x * w.x + vq.y * w.y;    // vq * conj(w)
            float vy = vq.y * w.x - vq.x * w.y;
            z[b2]        = make_float2(u.x + vx, u.y + vy);
            z[b2 + half] = make_float2(u.x - vx, u.y - vy);
        }
        mult >>= 1;
        __syncthreads();
    }

    // extract both rows' Hilbert transforms, write raw + flipped sections
    const size_t OFF = (size_t)Nk * 2 * Pk;
    float* raw0 = out + OFF + (size_t)r0 * 2 * Pk;
    float* raw1 = out + OFF + (size_t)r1 * 2 * Pk;
    float* flp0 = out + (size_t)r0 * 2 * Pk;
    float* flp1 = out + (size_t)r1 * 2 * Pk;
#pragma unroll
    for (int i = 0; i < CHB; i++) {
        int j = t + i * TB;
        float2 wv = z[j];
        float h0 = wv.y - x1[i];   // Im(w) - x1
        float h1 = x0[i] - wv.x;   // x0 - Re(w)
        raw0[j]      = x0[i];
        raw0[Pk + j] = h0;
        raw1[j]      = x1[i];
        raw1[Pk + j] = h1;
        int jf = Pk - 1 - j;
        flp0[jf]      = x0[i];
        flp0[Pk + jf] = h0;
        flp1[jf]      = x1[i];
        flp1[Pk + jf] = h1;
    }
}

// ---------------------------------------------------------------------------
// Launch
// ---------------------------------------------------------------------------
extern "C" void kernel_launch(void* const* d_in, const int* in_sizes, int n_in,
                              void* d_out, int out_size) {
    const float* start_ = (const float*)d_in[0];
    const float* end_   = (const float*)d_in[1];
    const float* stdv   = (const float*)d_in[2];
    const float* lob    = (const float*)d_in[3];
    const float* upb    = (const float*)d_in[4];
    const int*   win    = (const int*)  d_in[5];
    const float* scl    = (const float*)d_in[6];
    const float* noise  = (const float*)d_in[7];
    const float* omit   = (const float*)d_in[8];
    const float* ppm    = (const float*)d_in[9];
    const float* rng    = (const float*)d_in[10];
    float* out = (float*)d_out;

    const int SMEM_A = Lk * 4 + (Lk + 1) * 8 + 16 * 8 + 8 * 4 + 2 * 4;  // ~49.3 KB
    const int SMEM_B = Pk * 8 + (Pk / 2) * 8;                            // 96 KB

    cudaFuncSetAttribute(stageA, cudaFuncAttributeMaxDynamicSharedMemorySize, SMEM_A);
    cudaFuncSetAttribute(stageB, cudaFuncAttributeMaxDynamicSharedMemorySize, SMEM_B);

    twiddle_init<<<(Pk / 2 + 255) / 256, 256>>>();
    stageA<<<Nk, TA, SMEM_A>>>(start_, end_, stdv, lob, upb, win, scl,
                               noise, omit, ppm, rng);
    stageB<<<Nk / 2, TB, SMEM_B>>>(out);
}

// round 2
// speedup vs baseline: 2.8067x; 2.8067x over previous
#include <cuda_runtime.h>
#include <math.h>

#define Nk 1024
#define Lk 4096
#define Pk 8192
#define TA 256
#define CHA (Lk/TA)     // 16 elements per thread in stage A
#define TB 512

// Scratch (no cudaMalloc allowed)
__device__ float  g_acq[(size_t)Nk * Pk];     // 32 MB
__device__ float2 g_tw[Pk / 2];               // 32 KB: exp(-2*pi*i*r/P), r in [0, P/2)

// ---------------------------------------------------------------------------
// complex helpers
// ---------------------------------------------------------------------------
__device__ __forceinline__ float2 cmul(float2 a, float2 b) {
    return make_float2(fmaf(a.x, b.x, -a.y * b.y), fmaf(a.x, b.y, a.y * b.x));
}
__device__ __forceinline__ float2 cmulc(float2 a, float2 b) {   // a * conj(b)
    return make_float2(fmaf(a.x, b.x, a.y * b.y), fmaf(a.y, b.x, -a.x * b.y));
}
// twiddle fetch: g_tw holds first half; second half is the negation
__device__ __forceinline__ float2 TW(int idx) {
    if (idx < Pk / 2) return __ldg(&g_tw[idx]);
    float2 u = __ldg(&g_tw[idx - Pk / 2]);
    return make_float2(-u.x, -u.y);
}
// conflict-free shared swizzle (bijective; uniform within every warp access)
__device__ __forceinline__ int SW(int e) {
    return e ^ (((e >> 5) & 15) << 1);
}

// forward radix-4 DIF butterfly (in-place on 4 refs), twiddles w^j, w^2j, w^3j
__device__ __forceinline__ void bf4_fwd(float2& z0, float2& z1, float2& z2, float2& z3,
                                        float2 w1, float2 w2, float2 w3) {
    float Ax = z0.x + z2.x, Ay = z0.y + z2.y;
    float Cx = z0.x - z2.x, Cy = z0.y - z2.y;
    float Bx = z1.x + z3.x, By = z1.y + z3.y;
    float Dx = z1.x - z3.x, Dy = z1.y - z3.y;
    z0 = make_float2(Ax + Bx, Ay + By);
    float2 e1 = make_float2(Cx + Dy, Cy - Dx);   // C - iD
    float2 e2 = make_float2(Ax - Bx, Ay - By);
    float2 e3 = make_float2(Cx - Dy, Cy + Dx);   // C + iD
    z1 = cmul(e1, w1);
    z2 = cmul(e2, w2);
    z3 = cmul(e3, w3);
}

// inverse radix-4 DIT butterfly, conj twiddles applied to inputs 1..3
__device__ __forceinline__ void bf4_inv(float2& z0, float2& z1, float2& z2, float2& z3,
                                        float2 w1, float2 w2, float2 w3) {
    float2 t1 = cmulc(z1, w1);
    float2 t2 = cmulc(z2, w2);
    float2 t3 = cmulc(z3, w3);
    float Ax = z0.x + t2.x, Ay = z0.y + t2.y;
    float Cx = z0.x - t2.x, Cy = z0.y - t2.y;
    float Bx = t1.x + t3.x, By = t1.y + t3.y;
    float Dx = t1.x - t3.x, Dy = t1.y - t3.y;
    z0 = make_float2(Ax + Bx, Ay + By);
    z1 = make_float2(Cx - Dy, Cy + Dx);          // C + iD
    z2 = make_float2(Ax - Bx, Ay - By);
    z3 = make_float2(Cx + Dy, Cy - Dx);          // C - iD
}

// ---------------------------------------------------------------------------
// Block helpers (stage A)
// ---------------------------------------------------------------------------
__device__ __forceinline__ double blockExScan(double x, double* wsum, double* woff) {
    const unsigned full = 0xffffffffu;
    int lane = threadIdx.x & 31, wid = threadIdx.x >> 5;
    int nw = blockDim.x >> 5;
    double inc = x;
#pragma unroll
    for (int o = 1; o < 32; o <<= 1) {
        double y = __shfl_up_sync(full, inc, o);
        if (lane >= o) inc += y;
    }
    if (lane == 31) wsum[wid] = inc;
    __syncthreads();
    if (threadIdx.x == 0) {
        double run = 0.0;
        for (int i = 0; i < nw; i++) { double t = wsum[i]; woff[i] = run; run += t; }
    }
    __syncthreads();
    double r = woff[wid] + inc - x;
    __syncthreads();
    return r;
}

__device__ __forceinline__ float blockMax(float x, float* red) {
    const unsigned full = 0xffffffffu;
    int lane = threadIdx.x & 31, wid = threadIdx.x >> 5;
    int nw = blockDim.x >> 5;
#pragma unroll
    for (int o = 16; o > 0; o >>= 1)
        x = fmaxf(x, __shfl_xor_sync(full, x, o));
    if (lane == 0) red[wid] = x;
    __syncthreads();
    if (threadIdx.x == 0) {
        float m = red[0];
        for (int i = 1; i < nw; i++) m = fmaxf(m, red[i]);
        red[0] = m;
    }
    __syncthreads();
    float r = red[0];
    __syncthreads();
    return r;
}

// ---------------------------------------------------------------------------
// Stage A: walk -> smooth -> detrend/normalize -> interp (one block per row)
// block 0 also fills the twiddle table (consumed only by stageB, next kernel)
// ---------------------------------------------------------------------------
__global__ void __launch_bounds__(TA) stageA(
    const float* __restrict__ start_, const float* __restrict__ end_,
    const float* __restrict__ stdv,   const float* __restrict__ lob,
    const float* __restrict__ upb,    const int*   __restrict__ win,
    const float* __restrict__ scl,    const float* __restrict__ noise,
    const float* __restrict__ omit,   const float* __restrict__ ppm,
    const float* __restrict__ rng)
{
    extern __shared__ char smem[];
    float*  sA   = (float*)smem;                                  // Lk floats
    double* csD  = (double*)(smem + Lk * 4);                      // Lk+1 doubles
    double* wsum = (double*)(smem + Lk * 4 + (Lk + 1) * 8);       // 8 doubles
    double* woff = wsum + 8;                                      // 8 doubles
    float*  redf = (float*)(woff + 8);                            // 8 floats
    float*  sbc  = redf + 8;                                      // 2 floats

    const int n = blockIdx.x, t = threadIdx.x;

    if (n == 0) {   // fill twiddles: exp(-2*pi*i*k/Pk), k < Pk/2
        for (int i = t; i < Pk / 2; i += TA) {
            float s, c;
            sincospif(-(float)i / (float)(Pk / 2 / 2) * 0.5f, &s, &c);  // -pi*i/4096
            g_tw[i] = make_float2(c, s);
        }
    }

    const int base = t * CHA;
    const float stdn = stdv[n];
    const float inv = 1.0f / (float)(Lk - 1);

    // 1) steps + inclusive cumsum (fp64 accumulation)
    float v[CHA];
    double s = 0.0;
    const float4* nz4 = (const float4*)(noise + (size_t)n * Lk);
#pragma unroll
    for (int q = 0; q < CHA / 4; q++) {
        float4 nv = nz4[t * (CHA / 4) + q];
        float a0 = stdn * (nv.x - 0.5f), a1 = stdn * (nv.y - 0.5f);
        float a2 = stdn * (nv.z - 0.5f), a3 = stdn * (nv.w - 0.5f);
        v[q * 4 + 0] = a0; v[q * 4 + 1] = a1; v[q * 4 + 2] = a2; v[q * 4 + 3] = a3;
        s += (double)a0 + (double)a1 + (double)a2 + (double)a3;
    }
    double off = blockExScan(s, wsum, woff);
#pragma unroll
    for (int i = 0; i < CHA; i++) { off += (double)v[i]; sA[base + i] = (float)off; }
    __syncthreads();

    // 2) detrend walk, find span
    const float r0 = sA[0], rN = sA[Lk - 1];
    float mn = 1e30f, mx = -1e30f;
#pragma unroll
    for (int i = 0; i < CHA; i++) {
        int idx = base + i;
        float tt = (float)idx * inv;
        float d = sA[idx] - (r0 + (rN - r0) * tt);
        v[i] = d;
        mn = fminf(mn, d); mx = fmaxf(mx, d);
    }
    float gmx = blockMax(mx, redf);
    float gmn = -blockMax(-mn, redf);
    float span = gmx - gmn;
    const float lo = lob[n], up = upb[n];
    const float f = 1.0f / fmaxf(1.0f, span / (up - lo));
    const float st = start_[n], en = end_[n];

    // 3) squeeze + reflect + re-add trend
    double s2 = 0.0;
#pragma unroll
    for (int i = 0; i < CHA; i++) {
        int idx = base + i;
        float tt = (float)idx * inv;
        float tr = st + (en - st) * tt;
        float d = v[i] * f;
        float ub = up - tr, lb2 = lo - tr;
        float over = d - ub;
        if (over >= 0.0f) d = ub - over;
        float under = lb2 - d;
        if (under >= 0.0f) d = lb2 + under;
        float w = tr + d;
        v[i] = w;
        s2 += (double)w;
    }
    double off2 = blockExScan(s2, wsum, woff);
#pragma unroll
    for (int i = 0; i < CHA; i++) { csD[base + i] = off2; off2 += (double)v[i]; }
    if (t == TA - 1) csD[Lk] = off2;
    __syncthreads();

    // 4) box smoothing via prefix sums
    const int w = win[n];
    const int h2 = w >> 1;
    const double invw = 1.0 / (double)w;
#pragma unroll
    for (int i = 0; i < CHA; i++) {
        int idx = base + i;
        int loI = idx - h2;
        int hiI = loI + w;
        loI = max(0, min(loI, Lk));
        hiI = max(0, min(hiI, Lk));
        v[i] = (float)((csD[hiI] - csD[loI]) * invw);
    }
    if (t == 0)      sbc[0] = v[0];
    if (t == TA - 1) sbc[1] = v[CHA - 1];
    __syncthreads();
    const float b0 = sbc[0], bL = sbc[1];

    // 5) detrend smoothed + normalize + omit + scale
    float mxa = 0.0f;
#pragma unroll
    for (int i = 0; i < CHA; i++) {
        int idx = base + i;
        float tt = (float)idx * inv;
        float c = v[i] - (b0 + (bL - b0) * tt);
        v[i] = c;
        mxa = fmaxf(mxa, fabsf(c));
    }
    float denom = blockMax(mxa, redf);
    if (denom == 0.0f) denom = 1.0f;
    const float g = omit[n] * scl[n] / denom;
#pragma unroll
    for (int i = 0; i < CHA; i++) sA[base + i] = v[i] * g;
    __syncthreads();

    // 6) linear interp onto acquired ppm axis
    const float plo = rng[0], phi = rng[1];
    const float kk = (float)(Lk - 1) / (phi - plo);
    float* acq = g_acq + (size_t)n * Pk;
    for (int p = t; p < Pk; p += TA) {
        float pv = ppm[p];
        float o = 0.0f;
        if (pv >= plo && pv <= phi) {
            float pos = (pv - plo) * kk;
            int i0 = (int)pos;
            if (i0 > Lk - 2) i0 = Lk - 2;
            float fr = pos - (float)i0;
            float a = sA[i0];
            o = a + (sA[i0 + 1] - a) * fr;
        }
        acq[p] = o;
    }
}

// ---------------------------------------------------------------------------
// Stage B: pair-packed Hilbert, register-blocked mixed-radix FFT
// 8192 = 4*4 | 4*4 | 4*4*2, two radix-4 stages fused per shared round-trip,
// middle radix-2 + H + radix-2 fused via warp shuffles. One block per 2 rows.
// ---------------------------------------------------------------------------
__global__ void __launch_bounds__(TB) stageB(float* __restrict__ out)
{
    extern __shared__ float2 sz[];   // Pk complex, swizzled

    const int t = threadIdx.x, blk = blockIdx.x;
    const int r0 = blk * 2, r1 = r0 + 1;
    const float* a0 = g_acq + (size_t)r0 * Pk;
    const float* a1 = g_acq + (size_t)r1 * Pk;

    float2 z[16];   // z[a*4+b]

    // ---- load (pack rows as complex) ----
#pragma unroll
    for (int a = 0; a < 4; a++)
#pragma unroll
        for (int b = 0; b < 4; b++) {
            int j = t + 512 * b + 2048 * a;
            z[a * 4 + b] = make_float2(__ldg(&a0[j]), __ldg(&a1[j]));
        }

    // ---- forward pass 1: stages L=8192 (over a), L=2048 (over b) ----
#pragma unroll
    for (int b = 0; b < 4; b++) {
        int j = t + 512 * b;
        bf4_fwd(z[b], z[4 + b], z[8 + b], z[12 + b], TW(j), TW(2 * j), TW(3 * j));
    }
    {
        float2 w1 = TW(4 * t), w2 = TW(8 * t), w3 = TW(12 * t);
#pragma unroll
        for (int a = 0; a < 4; a++)
            bf4_fwd(z[a * 4], z[a * 4 + 1], z[a * 4 + 2], z[a * 4 + 3], w1, w2, w3);
    }
#pragma unroll
    for (int a = 0; a < 4; a++)
#pragma unroll
        for (int b = 0; b < 4; b++)
            sz[SW(t + 512 * b + 2048 * a)] = z[a * 4 + b];
    __syncthreads();

    // ---- forward pass 2: stages L=512 (over a), L=128 (over b) ----
    const int seg = t >> 5, c = t & 31;
    const int base2 = seg * 512 + c;
#pragma unroll
    for (int a = 0; a < 4; a++)
#pragma unroll
        for (int b = 0; b < 4; b++)
            z[a * 4 + b] = sz[SW(base2 + 128 * a + 32 * b)];
#pragma unroll
    for (int b = 0; b < 4; b++) {
        int j = 32 * b + c;
        bf4_fwd(z[b], z[4 + b], z[8 + b], z[12 + b], TW(16 * j), TW(32 * j), TW(48 * j));
    }
    {
        float2 w1 = TW(64 * c), w2 = TW(128 * c), w3 = TW(192 * c);
#pragma unroll
        for (int a = 0; a < 4; a++)
            bf4_fwd(z[a * 4], z[a * 4 + 1], z[a * 4 + 2], z[a * 4 + 3], w1, w2, w3);
    }
    __syncthreads();   // sz reads done before overwrite
#pragma unroll
    for (int a = 0; a < 4; a++)
#pragma unroll
        for (int b = 0; b < 4; b++)
            sz[SW(base2 + 128 * a + 32 * b)] = z[a * 4 + b];
    __syncthreads();

    // ---- forward pass 3: stages L=32 (over a), L=8 (over b) ----
    const int g = t >> 1, d = t & 1;
    const int base3 = 32 * g + d;
#pragma unroll
    for (int a = 0; a < 4; a++)
#pragma unroll
        for (int b = 0; b < 4; b++)
            z[a * 4 + b] = sz[SW(base3 + 8 * a + 2 * b)];
#pragma unroll
    for (int b = 0; b < 4; b++) {
        int j = 2 * b + d;
        bf4_fwd(z[b], z[4 + b], z[8 + b], z[12 + b], TW(256 * j), TW(512 * j), TW(768 * j));
    }
    {
        float2 w1 = TW(1024 * d), w2 = TW(2048 * d), w3 = TW(3072 * d);
#pragma unroll
        for (int a = 0; a < 4; a++)
            bf4_fwd(z[a * 4], z[a * 4 + 1], z[a * 4 + 2], z[a * 4 + 3], w1, w2, w3);
    }

    // ---- radix-2 (L=2) + H-multiply + inverse radix-2, via shuffles ----
    // In this permuted order: fH = 1/P at p in {0,1}; 2/P at even p; 0 at odd p.
    {
        const unsigned full = 0xffffffffu;
        const float s1 = 1.0f / (float)Pk, s2v = 2.0f / (float)Pk;
#pragma unroll
        for (int r = 0; r < 16; r++) {
            float2 zv = z[r];
            float px = __shfl_xor_sync(full, zv.x, 1);
            float py = __shfl_xor_sync(full, zv.y, 1);
            float sx, sy;
            if (d == 0) { sx = zv.x + px; sy = zv.y + py; }
            else        { sx = px - zv.x; sy = py - zv.y; }
            int p = base3 + 8 * (r >> 2) + 2 * (r & 3);
            float fH = (d == 0) ? ((p == 0) ? s1 : s2v)
                                 : ((p == 1) ? s1 : 0.0f);
            sx *= fH; sy *= fH;
            float qx = __shfl_xor_sync(full, sx, 1);
            float qy = __shfl_xor_sync(full, sy, 1);
            if (d == 0) { zv.x = sx + qx; zv.y = sy + qy; }
            else        { zv.x = qx - sx; zv.y = qy - sy; }
            z[r] = zv;
        }
    }

    // ---- inverse pass 3: stages L=8 (over b), L=32 (over a) ----
    {
        float2 w1 = TW(1024 * d), w2 = TW(2048 * d), w3 = TW(3072 * d);
#pragma unroll
        for (int a = 0; a < 4; a++)
            bf4_inv(z[a * 4], z[a * 4 + 1], z[a * 4 + 2], z[a * 4 + 3], w1, w2, w3);
    }
#pragma unroll
    for (int b = 0; b < 4; b++) {
        int j = 2 * b + d;
        bf4_inv(z[b], z[4 + b], z[8 + b], z[12 + b], TW(256 * j), TW(512 * j), TW(768 * j));
    }
#pragma unroll
    for (int a = 0; a < 4; a++)
#pragma unroll
        for (int b = 0; b < 4; b++)
            sz[SW(base3 + 8 * a + 2 * b)] = z[a * 4 + b];
    __syncthreads();

    // ---- inverse pass 2: stages L=128 (over b), L=512 (over a) ----
#pragma unroll
    for (int a = 0; a < 4; a++)
#pragma unroll
        for (int b = 0; b < 4; b++)
            z[a * 4 + b] = sz[SW(base2 + 128 * a + 32 * b)];
    {
        float2 w1 = TW(64 * c), w2 = TW(128 * c), w3 = TW(192 * c);
#pragma unroll
        for (int a = 0; a < 4; a++)
            bf4_inv(z[a * 4], z[a * 4 + 1], z[a * 4 + 2], z[a * 4 + 3], w1, w2, w3);
    }
#pragma unroll
    for (int b = 0; b < 4; b++) {
        int j = 32 * b + c;
        bf4_inv(z[b], z[4 + b], z[8 + b], z[12 + b], TW(16 * j), TW(32 * j), TW(48 * j));
    }
    __syncthreads();
#pragma unroll
    for (int a = 0; a < 4; a++)
#pragma unroll
        for (int b = 0; b < 4; b++)
            sz[SW(base2 + 128 * a + 32 * b)] = z[a * 4 + b];
    __syncthreads();

    // ---- inverse pass 1: stages L=2048 (over b), L=8192 (over a) ----
#pragma unroll
    for (int a = 0; a < 4; a++)
#pragma unroll
        for (int b = 0; b < 4; b++)
            z[a * 4 + b] = sz[SW(t + 512 * b + 2048 * a)];
    {
        float2 w1 = TW(4 * t), w2 = TW(8 * t), w3 = TW(12 * t);
#pragma unroll
        for (int a = 0; a < 4; a++)
            bf4_inv(z[a * 4], z[a * 4 + 1], z[a * 4 + 2], z[a * 4 + 3], w1, w2, w3);
    }
#pragma unroll
    for (int b = 0; b < 4; b++) {
        int j = t + 512 * b;
        bf4_inv(z[b], z[4 + b], z[8 + b], z[12 + b], TW(j), TW(2 * j), TW(3 * j));
    }

    // ---- unpack both rows' analytic signals, write raw + flipped sections ----
    const size_t OFF = (size_t)Nk * 2 * Pk;
    float* raw0 = out + OFF + (size_t)r0 * 2 * Pk;
    float* raw1 = out + OFF + (size_t)r1 * 2 * Pk;
    float* flp0 = out + (size_t)r0 * 2 * Pk;
    float* flp1 = out + (size_t)r1 * 2 * Pk;
#pragma unroll
    for (int a = 0; a < 4; a++)
#pragma unroll
        for (int b = 0; b < 4; b++) {
            int j = t + 512 * b + 2048 * a;
            float x0 = __ldg(&a0[j]);
            float x1 = __ldg(&a1[j]);
            float2 wv = z[a * 4 + b];
            float h0 = wv.y - x1;   // Im(w) - x1
            float h1 = x0 - wv.x;   // x0 - Re(w)
            raw0[j]      = x0;
            raw0[Pk + j] = h0;
            raw1[j]      = x1;
            raw1[Pk + j] = h1;
            int jf = Pk - 1 - j;
            flp0[jf]      = x0;
            flp0[Pk + jf] = h0;
            flp1[jf]      = x1;
            flp1[Pk + jf] = h1;
        }
}

// ---------------------------------------------------------------------------
// Launch
// ---------------------------------------------------------------------------
extern "C" void kernel_launch(void* const* d_in, const int* in_sizes, int n_in,
                              void* d_out, int out_size) {
    const float* start_ = (const float*)d_in[0];
    const float* end_   = (const float*)d_in[1];
    const float* stdv   = (const float*)d_in[2];
    const float* lob    = (const float*)d_in[3];
    const float* upb    = (const float*)d_in[4];
    const int*   win    = (const int*)  d_in[5];
    const float* scl    = (const float*)d_in[6];
    const float* noise  = (const float*)d_in[7];
    const float* omit   = (const float*)d_in[8];
    const float* ppm    = (const float*)d_in[9];
    const float* rng    = (const float*)d_in[10];
    float* out = (float*)d_out;

    const int SMEM_A = Lk * 4 + (Lk + 1) * 8 + 16 * 8 + 8 * 4 + 2 * 4;  // ~49.3 KB
    const int SMEM_B = Pk * 8;                                           // 64 KB

    cudaFuncSetAttribute(stageA, cudaFuncAttributeMaxDynamicSharedMemorySize, SMEM_A);
    cudaFuncSetAttribute(stageB, cudaFuncAttributeMaxDynamicSharedMemorySize, SMEM_B);

    stageA<<<Nk, TA, SMEM_A>>>(start_, end_, stdv, lob, upb, win, scl,
                               noise, omit, ppm, rng);
    stageB<<<Nk / 2, TB, SMEM_B>>>(out);
}

// round 3
// speedup vs baseline: 2.8462x; 1.0141x over previous
#include <cuda_runtime.h>
#include <math.h>

#define Nk 1024
#define Lk 4096
#define Pk 8192
#define TA 256
#define CHA (Lk/TA)     // 16 elements per thread in stage A
#define TB 512

// padded shared indexing (kills 16-way conflicts of the blocked layout)
#define IXF(i) ((i) + ((i) >> 5))
#define IXD(i) ((i) + ((i) >> 4))
#define SZF (Lk + Lk/32 + 4)        // 4228 floats
#define SZD (Lk + 1 + Lk/16 + 4)    // 4357 doubles

// Scratch (no cudaMalloc allowed)
__device__ float  g_acq[(size_t)Nk * Pk];     // 32 MB (L2-resident)
__device__ float2 g_tw[Pk / 2];               // 32 KB: exp(-2*pi*i*r/P)

// ---------------------------------------------------------------------------
// complex helpers
// ---------------------------------------------------------------------------
__device__ __forceinline__ float2 cmul(float2 a, float2 b) {
    return make_float2(fmaf(a.x, b.x, -a.y * b.y), fmaf(a.x, b.y, a.y * b.x));
}
__device__ __forceinline__ float2 cmulc(float2 a, float2 b) {   // a * conj(b)
    return make_float2(fmaf(a.x, b.x, a.y * b.y), fmaf(a.y, b.x, -a.x * b.y));
}
__device__ __forceinline__ float2 TW(int idx) {
    if (idx < Pk / 2) return __ldg(&g_tw[idx]);
    float2 u = __ldg(&g_tw[idx - Pk / 2]);
    return make_float2(-u.x, -u.y);
}
__device__ __forceinline__ int SW(int e) {
    return e ^ (((e >> 5) & 15) << 1);
}

__device__ __forceinline__ void bf4_fwd(float2& z0, float2& z1, float2& z2, float2& z3,
                                        float2 w1, float2 w2, float2 w3) {
    float Ax = z0.x + z2.x, Ay = z0.y + z2.y;
    float Cx = z0.x - z2.x, Cy = z0.y - z2.y;
    float Bx = z1.x + z3.x, By = z1.y + z3.y;
    float Dx = z1.x - z3.x, Dy = z1.y - z3.y;
    z0 = make_float2(Ax + Bx, Ay + By);
    float2 e1 = make_float2(Cx + Dy, Cy - Dx);
    float2 e2 = make_float2(Ax - Bx, Ay - By);
    float2 e3 = make_float2(Cx - Dy, Cy + Dx);
    z1 = cmul(e1, w1);
    z2 = cmul(e2, w2);
    z3 = cmul(e3, w3);
}

__device__ __forceinline__ void bf4_inv(float2& z0, float2& z1, float2& z2, float2& z3,
                                        float2 w1, float2 w2, float2 w3) {
    float2 t1 = cmulc(z1, w1);
    float2 t2 = cmulc(z2, w2);
    float2 t3 = cmulc(z3, w3);
    float Ax = z0.x + t2.x, Ay = z0.y + t2.y;
    float Cx = z0.x - t2.x, Cy = z0.y - t2.y;
    float Bx = t1.x + t3.x, By = t1.y + t3.y;
    float Dx = t1.x - t3.x, Dy = t1.y - t3.y;
    z0 = make_float2(Ax + Bx, Ay + By);
    z1 = make_float2(Cx - Dy, Cy + Dx);
    z2 = make_float2(Ax - Bx, Ay - By);
    z3 = make_float2(Cx + Dy, Cy - Dx);
}

// ---------------------------------------------------------------------------
// Block helpers (stage A)
// ---------------------------------------------------------------------------
__device__ __forceinline__ double blockExScan(double x, double* wsum, double* woff) {
    const unsigned full = 0xffffffffu;
    int lane = threadIdx.x & 31, wid = threadIdx.x >> 5;
    int nw = blockDim.x >> 5;
    double inc = x;
#pragma unroll
    for (int o = 1; o < 32; o <<= 1) {
        double y = __shfl_up_sync(full, inc, o);
        if (lane >= o) inc += y;
    }
    if (lane == 31) wsum[wid] = inc;
    __syncthreads();
    if (threadIdx.x == 0) {
        double run = 0.0;
        for (int i = 0; i < nw; i++) { double t = wsum[i]; woff[i] = run; run += t; }
    }
    __syncthreads();
    double r = woff[wid] + inc - x;
    __syncthreads();
    return r;
}

__device__ __forceinline__ float blockMax(float x, float* red) {
    const unsigned full = 0xffffffffu;
    int lane = threadIdx.x & 31, wid = threadIdx.x >> 5;
    int nw = blockDim.x >> 5;
#pragma unroll
    for (int o = 16; o > 0; o >>= 1)
        x = fmaxf(x, __shfl_xor_sync(full, x, o));
    if (lane == 0) red[wid] = x;
    __syncthreads();
    if (threadIdx.x == 0) {
        float m = red[0];
        for (int i = 1; i < nw; i++) m = fmaxf(m, red[i]);
        red[0] = m;
    }
    __syncthreads();
    float r = red[0];
    __syncthreads();
    return r;
}

// ---------------------------------------------------------------------------
// Stage A: walk -> smooth -> detrend/normalize -> interp (one block per row)
// register-resident pipeline; shared only for staging / prefix-sum / interp src
// ---------------------------------------------------------------------------
__global__ void __launch_bounds__(TA) stageA(
    const float* __restrict__ start_, const float* __restrict__ end_,
    const float* __restrict__ stdv,   const float* __restrict__ lob,
    const float* __restrict__ upb,    const int*   __restrict__ win,
    const float* __restrict__ scl,    const float* __restrict__ noise,
    const float* __restrict__ omit,   const float* __restrict__ ppm,
    const float* __restrict__ rng)
{
    extern __shared__ char smem[];
    float*  sAp  = (float*)smem;                           // SZF floats (padded)
    double* csD  = (double*)(smem + SZF * 4);              // SZD doubles (padded)
    double* wsum = (double*)(smem + SZF * 4 + SZD * 8);    // 8
    double* woff = wsum + 8;                               // 8
    float*  redf = (float*)(woff + 8);                     // 8
    float*  sbc  = redf + 8;                               // 4

    const int n = blockIdx.x, t = threadIdx.x;

    if (n == 0) {   // fill twiddles: exp(-2*pi*i*k/Pk), k < Pk/2
        for (int i = t; i < Pk / 2; i += TA) {
            float s, c;
            sincospif(-(float)i / (float)(Pk / 2), &s, &c);  // -pi*i/4096
            g_tw[i] = make_float2(c, s);
        }
    }

    const int base = t * CHA;
    const float stdn = stdv[n];
    const float inv = 1.0f / (float)(Lk - 1);

    // 1) coalesced noise load -> steps into padded shared
    const float4* nz4 = (const float4*)(noise + (size_t)n * Lk);
#pragma unroll
    for (int q = 0; q < CHA / 4; q++) {
        int i4 = q * TA + t;                 // coalesced float4 index
        float4 nv = nz4[i4];
        int e = i4 * 4;
        sAp[IXF(e + 0)] = stdn * (nv.x - 0.5f);
        sAp[IXF(e + 1)] = stdn * (nv.y - 0.5f);
        sAp[IXF(e + 2)] = stdn * (nv.z - 0.5f);
        sAp[IXF(e + 3)] = stdn * (nv.w - 0.5f);
    }
    __syncthreads();

    // blocked read (conflict-free with padding) + tree-summed fp64 accumulation
    float v[CHA];
    double s = 0.0;
#pragma unroll
    for (int i = 0; i < CHA; i += 4) {
        v[i]     = sAp[IXF(base + i)];
        v[i + 1] = sAp[IXF(base + i + 1)];
        v[i + 2] = sAp[IXF(base + i + 2)];
        v[i + 3] = sAp[IXF(base + i + 3)];
        s += ((double)v[i] + (double)v[i + 1]) + ((double)v[i + 2] + (double)v[i + 3]);
    }
    double off = blockExScan(s, wsum, woff);
#pragma unroll
    for (int i = 0; i < CHA; i++) { off += (double)v[i]; v[i] = (float)off; }
    // broadcast walk endpoints
    if (t == 0)      sbc[0] = v[0];
    if (t == TA - 1) sbc[1] = v[CHA - 1];
    __syncthreads();
    const float r0 = sbc[0], rN = sbc[1];

    // 2) detrend walk (in regs), find span
    float mn = 1e30f, mx = -1e30f;
#pragma unroll
    for (int i = 0; i < CHA; i++) {
        float tt = (float)(base + i) * inv;
        float d = v[i] - (r0 + (rN - r0) * tt);
        v[i] = d;
        mn = fminf(mn, d); mx = fmaxf(mx, d);
    }
    float gmx = blockMax(mx, redf);
    float gmn = -blockMax(-mn, redf);
    float span = gmx - gmn;
    const float lo = lob[n], up = upb[n];
    const float f = 1.0f / fmaxf(1.0f, span / (up - lo));
    const float st = start_[n], en = end_[n];

    // 3) squeeze + reflect + re-add trend (in regs)
    double s2 = 0.0;
#pragma unroll
    for (int i = 0; i < CHA; i++) {
        float tt = (float)(base + i) * inv;
        float tr = st + (en - st) * tt;
        float d = v[i] * f;
        float ub = up - tr, lb2 = lo - tr;
        float over = d - ub;
        if (over >= 0.0f) d = ub - over;
        float under = lb2 - d;
        if (under >= 0.0f) d = lb2 + under;
        v[i] = tr + d;
        s2 += (double)v[i];
    }
    double off2 = blockExScan(s2, wsum, woff);
#pragma unroll
    for (int i = 0; i < CHA; i++) { csD[IXD(base + i)] = off2; off2 += (double)v[i]; }
    if (t == TA - 1) csD[IXD(Lk)] = off2;
    __syncthreads();

    // 4) box smoothing via prefix sums (zero padding == clamp)
    const int w = win[n];
    const int h2 = w >> 1;
    const double invw = 1.0 / (double)w;
#pragma unroll
    for (int i = 0; i < CHA; i++) {
        int idx = base + i;
        int loI = idx - h2;
        int hiI = loI + w;
        loI = max(0, min(loI, Lk));
        hiI = max(0, min(hiI, Lk));
        v[i] = (float)((csD[IXD(hiI)] - csD[IXD(loI)]) * invw);
    }
    if (t == 0)      sbc[2] = v[0];
    if (t == TA - 1) sbc[3] = v[CHA - 1];
    __syncthreads();
    const float b0 = sbc[2], bL = sbc[3];

    // 5) detrend smoothed + normalize + omit + scale
    float mxa = 0.0f;
#pragma unroll
    for (int i = 0; i < CHA; i++) {
        float tt = (float)(base + i) * inv;
        float c = v[i] - (b0 + (bL - b0) * tt);
        v[i] = c;
        mxa = fmaxf(mxa, fabsf(c));
    }
    float denom = blockMax(mxa, redf);
    if (denom == 0.0f) denom = 1.0f;
    const float g = omit[n] * scl[n] / denom;
#pragma unroll
    for (int i = 0; i < CHA; i++) sAp[IXF(base + i)] = v[i] * g;
    __syncthreads();

    // 6) linear interp onto acquired ppm axis
    const float plo = rng[0], phi = rng[1];
    const float kk = (float)(Lk - 1) / (phi - plo);
    float* acq = g_acq + (size_t)n * Pk;
    for (int p = t; p < Pk; p += TA) {
        float pv = ppm[p];
        float o = 0.0f;
        if (pv >= plo && pv <= phi) {
            float pos = (pv - plo) * kk;
            int i0 = (int)pos;
            if (i0 > Lk - 2) i0 = Lk - 2;
            float fr = pos - (float)i0;
            float a = sAp[IXF(i0)];
            o = a + (sAp[IXF(i0 + 1)] - a) * fr;
        }
        acq[p] = o;
    }
}

// ---------------------------------------------------------------------------
// Stage B: pair-packed Hilbert, register-blocked mixed-radix FFT
// ---------------------------------------------------------------------------
__global__ void __launch_bounds__(TB, 2) stageB(float* __restrict__ out)
{
    extern __shared__ float2 sz[];   // Pk complex, swizzled

    const int t = threadIdx.x, blk = blockIdx.x;
    const int r0 = blk * 2, r1 = r0 + 1;
    const float* a0 = g_acq + (size_t)r0 * Pk;
    const float* a1 = g_acq + (size_t)r1 * Pk;

    float2 z[16];   // z[a*4+b]

    // ---- load (pack rows as complex) ----
#pragma unroll
    for (int a = 0; a < 4; a++)
#pragma unroll
        for (int b = 0; b < 4; b++) {
            int j = t + 512 * b + 2048 * a;
            z[a * 4 + b] = make_float2(__ldg(&a0[j]), __ldg(&a1[j]));
        }

    // ---- forward pass 1: stages L=8192 (over a), L=2048 (over b) ----
#pragma unroll
    for (int b = 0; b < 4; b++) {
        int j = t + 512 * b;
        bf4_fwd(z[b], z[4 + b], z[8 + b], z[12 + b], TW(j), TW(2 * j), TW(3 * j));
    }
    {
        float2 w1 = TW(4 * t), w2 = TW(8 * t), w3 = TW(12 * t);
#pragma unroll
        for (int a = 0; a < 4; a++)
            bf4_fwd(z[a * 4], z[a * 4 + 1], z[a * 4 + 2], z[a * 4 + 3], w1, w2, w3);
    }
#pragma unroll
    for (int a = 0; a < 4; a++)
#pragma unroll
        for (int b = 0; b < 4; b++)
            sz[SW(t + 512 * b + 2048 * a)] = z[a * 4 + b];
    __syncthreads();

    // ---- forward pass 2: stages L=512 (over a), L=128 (over b) ----
    const int seg = t >> 5, c = t & 31;
    const int base2 = seg * 512 + c;
#pragma unroll
    for (int a = 0; a < 4; a++)
#pragma unroll
        for (int b = 0; b < 4; b++)
            z[a * 4 + b] = sz[SW(base2 + 128 * a + 32 * b)];
#pragma unroll
    for (int b = 0; b < 4; b++) {
        int j = 32 * b + c;
        bf4_fwd(z[b], z[4 + b], z[8 + b], z[12 + b], TW(16 * j), TW(32 * j), TW(48 * j));
    }
    {
        float2 w1 = TW(64 * c), w2 = TW(128 * c), w3 = TW(192 * c);
#pragma unroll
        for (int a = 0; a < 4; a++)
            bf4_fwd(z[a * 4], z[a * 4 + 1], z[a * 4 + 2], z[a * 4 + 3], w1, w2, w3);
    }
    __syncthreads();
#pragma unroll
    for (int a = 0; a < 4; a++)
#pragma unroll
        for (int b = 0; b < 4; b++)
            sz[SW(base2 + 128 * a + 32 * b)] = z[a * 4 + b];
    __syncthreads();

    // ---- forward pass 3: stages L=32 (over a), L=8 (over b) ----
    const int g = t >> 1, d = t & 1;
    const int base3 = 32 * g + d;
#pragma unroll
    for (int a = 0; a < 4; a++)
#pragma unroll
        for (int b = 0; b < 4; b++)
            z[a * 4 + b] = sz[SW(base3 + 8 * a + 2 * b)];
#pragma unroll
    for (int b = 0; b < 4; b++) {
        int j = 2 * b + d;
        bf4_fwd(z[b], z[4 + b], z[8 + b], z[12 + b], TW(256 * j), TW(512 * j), TW(768 * j));
    }
    {
        float2 w1 = TW(1024 * d), w2 = TW(2048 * d), w3 = TW(3072 * d);
#pragma unroll
        for (int a = 0; a < 4; a++)
            bf4_fwd(z[a * 4], z[a * 4 + 1], z[a * 4 + 2], z[a * 4 + 3], w1, w2, w3);
    }

    // ---- radix-2 (L=2) + H-multiply + inverse radix-2, via shuffles ----
    {
        const unsigned full = 0xffffffffu;
        const float s1 = 1.0f / (float)Pk, s2v = 2.0f / (float)Pk;
#pragma unroll
        for (int r = 0; r < 16; r++) {
            float2 zv = z[r];
            float px = __shfl_xor_sync(full, zv.x, 1);
            float py = __shfl_xor_sync(full, zv.y, 1);
            float sx, sy;
            if (d == 0) { sx = zv.x + px; sy = zv.y + py; }
            else        { sx = px - zv.x; sy = py - zv.y; }
            int p = base3 + 8 * (r >> 2) + 2 * (r & 3);
            float fH = (d == 0) ? ((p == 0) ? s1 : s2v)
                                 : ((p == 1) ? s1 : 0.0f);
            sx *= fH; sy *= fH;
            float qx = __shfl_xor_sync(full, sx, 1);
            float qy = __shfl_xor_sync(full, sy, 1);
            if (d == 0) { zv.x = sx + qx; zv.y = sy + qy; }
            else        { zv.x = qx - sx; zv.y = qy - sy; }
            z[r] = zv;
        }
    }

    // ---- inverse pass 3 ----
    {
        float2 w1 = TW(1024 * d), w2 = TW(2048 * d), w3 = TW(3072 * d);
#pragma unroll
        for (int a = 0; a < 4; a++)
            bf4_inv(z[a * 4], z[a * 4 + 1], z[a * 4 + 2], z[a * 4 + 3], w1, w2, w3);
    }
#pragma unroll
    for (int b = 0; b < 4; b++) {
        int j = 2 * b + d;
        bf4_inv(z[b], z[4 + b], z[8 + b], z[12 + b], TW(256 * j), TW(512 * j), TW(768 * j));
    }
#pragma unroll
    for (int a = 0; a < 4; a++)
#pragma unroll
        for (int b = 0; b < 4; b++)
            sz[SW(base3 + 8 * a + 2 * b)] = z[a * 4 + b];
    __syncthreads();

    // ---- inverse pass 2 ----
#pragma unroll
    for (int a = 0; a < 4; a++)
#pragma unroll
        for (int b = 0; b < 4; b++)
            z[a * 4 + b] = sz[SW(base2 + 128 * a + 32 * b)];
    {
        float2 w1 = TW(64 * c), w2 = TW(128 * c), w3 = TW(192 * c);
#pragma unroll
        for (int a = 0; a < 4; a++)
            bf4_inv(z[a * 4], z[a * 4 + 1], z[a * 4 + 2], z[a * 4 + 3], w1, w2, w3);
    }
#pragma unroll
    for (int b = 0; b < 4; b++) {
        int j = 32 * b + c;
        bf4_inv(z[b], z[4 + b], z[8 + b], z[12 + b], TW(16 * j), TW(32 * j), TW(48 * j));
    }
    __syncthreads();
#pragma unroll
    for (int a = 0; a < 4; a++)
#pragma unroll
        for (int b = 0; b < 4; b++)
            sz[SW(base2 + 128 * a + 32 * b)] = z[a * 4 + b];
    __syncthreads();

    // ---- inverse pass 1 ----
#pragma unroll
    for (int a = 0; a < 4; a++)
#pragma unroll
        for (int b = 0; b < 4; b++)
            z[a * 4 + b] = sz[SW(t + 512 * b + 2048 * a)];
    {
        float2 w1 = TW(4 * t), w2 = TW(8 * t), w3 = TW(12 * t);
#pragma unroll
        for (int a = 0; a < 4; a++)
            bf4_inv(z[a * 4], z[a * 4 + 1], z[a * 4 + 2], z[a * 4 + 3], w1, w2, w3);
    }
#pragma unroll
    for (int b = 0; b < 4; b++) {
        int j = t + 512 * b;
        bf4_inv(z[b], z[4 + b], z[8 + b], z[12 + b], TW(j), TW(2 * j), TW(3 * j));
    }

    // ---- unpack both rows, write raw + flipped sections ----
    const size_t OFF = (size_t)Nk * 2 * Pk;
    const size_t rb0 = (size_t)r0 * 2 * Pk;
    const size_t rb1 = (size_t)r1 * 2 * Pk;
#pragma unroll
    for (int a = 0; a < 4; a++)
#pragma unroll
        for (int b = 0; b < 4; b++) {
            int j = t + 512 * b + 2048 * a;
            float x0 = __ldg(&a0[j]);
            float x1 = __ldg(&a1[j]);
            float2 wv = z[a * 4 + b];
            float h0 = wv.y - x1;
            float h1 = x0 - wv.x;
            out[OFF + rb0 + j]      = x0;
            out[OFF + rb0 + Pk + j] = h0;
            out[OFF + rb1 + j]      = x1;
            out[OFF + rb1 + Pk + j] = h1;
            int jf = Pk - 1 - j;
            out[rb0 + jf]      = x0;
            out[rb0 + Pk + jf] = h0;
            out[rb1 + jf]      = x1;
            out[rb1 + Pk + jf] = h1;
        }
}

// ---------------------------------------------------------------------------
// Launch
// ---------------------------------------------------------------------------
extern "C" void kernel_launch(void* const* d_in, const int* in_sizes, int n_in,
                              void* d_out, int out_size) {
    const float* start_ = (const float*)d_in[0];
    const float* end_   = (const float*)d_in[1];
    const float* stdv   = (const float*)d_in[2];
    const float* lob    = (const float*)d_in[3];
    const float* upb    = (const float*)d_in[4];
    const int*   win    = (const int*)  d_in[5];
    const float* scl    = (const float*)d_in[6];
    const float* noise  = (const float*)d_in[7];
    const float* omit   = (const float*)d_in[8];
    const float* ppm    = (const float*)d_in[9];
    const float* rng    = (const float*)d_in[10];
    float* out = (float*)d_out;

    const int SMEM_A = SZF * 4 + SZD * 8 + 16 * 8 + 8 * 4 + 4 * 4;  // ~51.9 KB
    const int SMEM_B = Pk * 8;                                       // 64 KB

    cudaFuncSetAttribute(stageA, cudaFuncAttributeMaxDynamicSharedMemorySize, SMEM_A);
    cudaFuncSetAttribute(stageB, cudaFuncAttributeMaxDynamicSharedMemorySize, SMEM_B);

    stageA<<<Nk, TA, SMEM_A>>>(start_, end_, stdv, lob, upb, win, scl,
                               noise, omit, ppm, rng);
    stageB<<<Nk / 2, TB, SMEM_B>>>(out);
}